// round 1
// baseline (speedup 1.0000x reference)
#include <cuda_runtime.h>

// ShallowLSTM: B=8192, T=180, I=7, H=64, O=16
// Persistent per-block LSTM: each block owns TB=64 batch elements.
// gates[64,256] = [h | x | pad][64,72] @ Wd[72,256] per step, fp32 packed (f32x2),
// 2 batch elements per 64-bit lane. c kept in registers, h/x double-buffered in SMEM.

typedef unsigned long long ull;

#define T_STEPS 180
#define IDIM    7
#define HID     64
#define GATES   256      // 4*HID
#define KDIM    72       // 64 h + 7 x + 1 zero pad
#define TB      64       // batch per block
#define HSTR    34       // padded pair stride (even -> 16B alignment kept)
#define NTHR    256
#define ODIM    16

union U64 { ull u; float2 f; };

__device__ __forceinline__ ull fma2(ull a, ull b, ull c) {
    ull d;
    asm("fma.rn.f32x2 %0, %1, %2, %3;" : "=l"(d) : "l"(a), "l"(b), "l"(c));
    return d;
}

__device__ __forceinline__ float sigm(float x) {
    float e = __expf(-x);
    return __fdividef(1.0f, 1.0f + e);
}
__device__ __forceinline__ float tanh_f(float x) {
    float e = __expf(-2.0f * x);
    return __fdividef(1.0f - e, 1.0f + e);
}

__global__ void __launch_bounds__(NTHR, 1) lstm_fused(
    const float* __restrict__ x,
    const float* __restrict__ W_ih,
    const float* __restrict__ W_hh,
    const float* __restrict__ b_ih,
    const float* __restrict__ b_hh,
    const float* __restrict__ W_fc,
    const float* __restrict__ b_fc,
    float* __restrict__ out)
{
    extern __shared__ char smraw[];
    ull* Wd = (ull*)smraw;                 // [KDIM][GATES], each entry {w,w}
    ull* hs = Wd + KDIM * GATES;           // [2][KDIM][HSTR], pair-packed {b_even,b_odd}

    const int tid   = threadIdx.x;
    const int col   = tid & (HID - 1);     // h-column / gate column 0..63
    const int pg    = tid >> 6;            // pair-group 0..3 (8 pairs each)
    const int bbase = blockIdx.x * TB;

    // ---- load duplicated weights into SMEM (one-time) ----
    for (int idx = tid; idx < KDIM * GATES; idx += NTHR) {
        int k = idx >> 8;          // row (K index)
        int g = idx & (GATES - 1); // gate column
        float w = 0.0f;
        if (k < HID)             w = W_hh[g * HID + k];
        else if (k < HID + IDIM) w = W_ih[g * IDIM + (k - HID)];
        U64 u; u.f = make_float2(w, w);
        Wd[idx] = u.u;
    }
    // zero both h/x buffers (h(0)=0; pad row 71 stays zero forever)
    for (int idx = tid; idx < 2 * KDIM * HSTR; idx += NTHR)
        hs[idx] = 0ull;

    // ---- per-thread biases (packed) ----
    ull bias2[4];
    #pragma unroll
    for (int g = 0; g < 4; ++g) {
        float b = b_ih[g * HID + col] + b_hh[g * HID + col];
        U64 u; u.f = make_float2(b, b);
        bias2[g] = u.u;
    }

    const float* xp = nullptr;
    float xr[IDIM];
    if (tid < TB)
        xp = x + (size_t)(bbase + tid) * (T_STEPS * IDIM);

    __syncthreads();  // weights + zeroing visible

    // x(0) -> buffer 0 rows 64..70; prefetch x(1) into regs
    if (tid < TB) {
        #pragma unroll
        for (int i = 0; i < IDIM; ++i)
            ((float*)&hs[(HID + i) * HSTR + (tid >> 1)])[tid & 1] = xp[i];
        #pragma unroll
        for (int i = 0; i < IDIM; ++i)
            xr[i] = xp[IDIM + i];
    }
    __syncthreads();

    // persistent cell state (8 pairs = 16 batch elements per thread at column `col`)
    float2 cst[8];
    #pragma unroll
    for (int p = 0; p < 8; ++p) cst[p] = make_float2(0.f, 0.f);

    int cur = 0;
    for (int t = 0; t < T_STEPS; ++t) {
        const ull* hb = hs + cur * (KDIM * HSTR);
        ull*       hn = hs + (cur ^ 1) * (KDIM * HSTR);

        ull acc[4][8];
        #pragma unroll
        for (int g = 0; g < 4; ++g)
            #pragma unroll
            for (int p = 0; p < 8; ++p) acc[g][p] = bias2[g];

        // ---- GEMM: gates[col + 64g][16 batches] over K=72 ----
        #pragma unroll 4
        for (int k = 0; k < KDIM; ++k) {
            ull w0 = Wd[k * GATES + col];
            ull w1 = Wd[k * GATES + HID + col];
            ull w2 = Wd[k * GATES + 2 * HID + col];
            ull w3 = Wd[k * GATES + 3 * HID + col];
            const ulonglong2* hp = (const ulonglong2*)(hb + k * HSTR + pg * 8);
            ulonglong2 h01 = hp[0], h23 = hp[1], h45 = hp[2], h67 = hp[3];
            ull hv[8] = {h01.x, h01.y, h23.x, h23.y, h45.x, h45.y, h67.x, h67.y};
            #pragma unroll
            for (int p = 0; p < 8; ++p) {
                acc[0][p] = fma2(hv[p], w0, acc[0][p]);
                acc[1][p] = fma2(hv[p], w1, acc[1][p]);
                acc[2][p] = fma2(hv[p], w2, acc[2][p]);
                acc[3][p] = fma2(hv[p], w3, acc[3][p]);
            }
        }

        // ---- epilogue: nonlinearities, state update, h writeback ----
        #pragma unroll
        for (int p = 0; p < 8; ++p) {
            U64 ui, uf, ug, uo;
            ui.u = acc[0][p]; uf.u = acc[1][p]; ug.u = acc[2][p]; uo.u = acc[3][p];
            float ilo = sigm(ui.f.x),   ihi = sigm(ui.f.y);
            float flo = sigm(uf.f.x),   fhi = sigm(uf.f.y);
            float glo = tanh_f(ug.f.x), ghi = tanh_f(ug.f.y);
            float olo = sigm(uo.f.x),   ohi = sigm(uo.f.y);
            float clo = flo * cst[p].x + ilo * glo;
            float chi = fhi * cst[p].y + ihi * ghi;
            cst[p].x = clo; cst[p].y = chi;
            U64 hvv; hvv.f = make_float2(olo * tanh_f(clo), ohi * tanh_f(chi));
            hn[col * HSTR + pg * 8 + p] = hvv.u;
        }

        // x(t+1) -> next buffer; prefetch x(t+2)
        if (tid < TB) {
            #pragma unroll
            for (int i = 0; i < IDIM; ++i)
                ((float*)&hn[(HID + i) * HSTR + (tid >> 1)])[tid & 1] = xr[i];
            if (t + 2 < T_STEPS) {
                #pragma unroll
                for (int i = 0; i < IDIM; ++i)
                    xr[i] = xp[(t + 2) * IDIM + i];
            }
        }
        __syncthreads();
        cur ^= 1;
    }

    // ---- final FC: out[b,o] = h_last[b,:] . W_fc[o,:] + b_fc[o] ----
    // cur == 0 after 180 flips; h_last lives in buffer 0, rows 0..63.
    {
        const ull* hf = hs + cur * (KDIM * HSTR);
        int b_local = tid & 63;
        int og      = tid >> 6;       // 4 outputs per thread: o = og*4 .. og*4+3
        float acc_o[4];
        #pragma unroll
        for (int j = 0; j < 4; ++j) acc_o[j] = b_fc[og * 4 + j];
        for (int k = 0; k < HID; ++k) {
            float hv = ((const float*)&hf[k * HSTR + (b_local >> 1)])[b_local & 1];
            #pragma unroll
            for (int j = 0; j < 4; ++j)
                acc_o[j] += hv * W_fc[(og * 4 + j) * HID + k];
        }
        #pragma unroll
        for (int j = 0; j < 4; ++j)
            out[(size_t)(bbase + b_local) * ODIM + og * 4 + j] = acc_o[j];
    }
}

extern "C" void kernel_launch(void* const* d_in, const int* in_sizes, int n_in,
                              void* d_out, int out_size) {
    const float* x    = (const float*)d_in[0];
    const float* W_ih = (const float*)d_in[1];
    const float* W_hh = (const float*)d_in[2];
    const float* b_ih = (const float*)d_in[3];
    const float* b_hh = (const float*)d_in[4];
    const float* W_fc = (const float*)d_in[5];
    const float* b_fc = (const float*)d_in[6];
    float* out = (float*)d_out;

    int B = in_sizes[0] / (T_STEPS * IDIM);   // 8192
    int nblocks = B / TB;                      // 128

    size_t smem = (size_t)(KDIM * GATES + 2 * KDIM * HSTR) * sizeof(ull); // 186624 B
    cudaFuncSetAttribute(lstm_fused, cudaFuncAttributeMaxDynamicSharedMemorySize, (int)smem);

    lstm_fused<<<nblocks, NTHR, smem>>>(x, W_ih, W_hh, b_ih, b_hh, W_fc, b_fc, out);
}

// round 3
// speedup vs baseline: 2.1679x; 2.1679x over previous
#include <cuda_runtime.h>
#include <cuda_fp16.h>
#include <cstdint>

// ShallowLSTM via classic mma.sync (m16n8k16 fp16->fp32), generic PTX (no tcgen05).
// B=8192, T=180, I=7, H=64, O=16. 128 CTAs x 64 batch, 256 threads.
// K=160: [h_hi(64) | h_lo(64) | x_hi(7) x_lo(7) 1 1]; B has matching hi/lo weight
// blocks so all first-order fp16 quantization residues are corrected (fp32-class).
// Two independent 32-batch halves per CTA with named barriers -> MUFU/HMMA overlap.

#define T_STEPS 180
#define IDIM    7
#define HID     64
#define TB      64
#define NTHR    256
#define ODIM    16

#define SA      304           // A row stride bytes (144 halves + pad)
#define SB      336           // B row stride bytes (160 halves + pad)
#define ABUF    19456         // 64*SA
#define OFF_B   38912
#define OFF_HF  124928
#define OFF_WFC 142336
#define OFF_BFC 146432
#define SMEM_TOTAL 146496

__device__ __forceinline__ uint32_t smem_u32(const void* p) {
    uint32_t a;
    asm("{ .reg .u64 t; cvta.to.shared.u64 t, %1; cvt.u32.u64 %0, t; }" : "=r"(a) : "l"(p));
    return a;
}

#define LDSM4(r, addr) \
    asm volatile("ldmatrix.sync.aligned.m8n8.x4.shared.b16 {%0,%1,%2,%3}, [%4];" \
        : "=r"((r)[0]), "=r"((r)[1]), "=r"((r)[2]), "=r"((r)[3]) : "r"(addr))

#define MMA(d, a, b0, b1) \
    asm volatile("mma.sync.aligned.m16n8k16.row.col.f32.f16.f16.f32 " \
        "{%0,%1,%2,%3},{%4,%5,%6,%7},{%8,%9},{%0,%1,%2,%3};" \
        : "+f"((d)[0]), "+f"((d)[1]), "+f"((d)[2]), "+f"((d)[3]) \
        : "r"((a)[0]), "r"((a)[1]), "r"((a)[2]), "r"((a)[3]), "r"(b0), "r"(b1))

__global__ void __launch_bounds__(NTHR, 1) lstm_mma(
    const float* __restrict__ x,
    const float* __restrict__ W_ih,
    const float* __restrict__ W_hh,
    const float* __restrict__ b_ih,
    const float* __restrict__ b_hh,
    const float* __restrict__ W_fc,
    const float* __restrict__ b_fc,
    float* __restrict__ out)
{
    extern __shared__ char sm[];
    float* hf  = (float*)(sm + OFF_HF);
    float* wfc = (float*)(sm + OFF_WFC);
    float* bfc = (float*)(sm + OFF_BFC);

    const int tid  = threadIdx.x;
    const int w    = tid >> 5;
    const int lane = tid & 31;
    const int hid  = w >> 2;            // half 0: warps 0-3, half 1: warps 4-7
    const int wn   = w & 3;
    const int mrow = hid * 32;
    const int ncol = wn * 64;
    const int bbase = blockIdx.x * TB;

    // ---- build B [256 n][160 k] fp16 (n = 4*j + gate reorder) ----
    for (int idx = tid; idx < 256 * 160; idx += NTHR) {
        int n = idx / 160, k = idx - n * 160;
        int r = (n & 3) * 64 + (n >> 2);
        float v = 0.f; int lo = 0;
        if      (k < 64)  v = W_hh[r * 64 + k];
        else if (k < 128) { v = W_hh[r * 64 + (k - 64)]; lo = 1; }
        else if (k < 135) v = W_ih[r * 7 + (k - 128)];
        else if (k < 142) v = W_ih[r * 7 + (k - 135)];
        else if (k == 142) v = b_ih[r] + b_hh[r];
        else if (k == 143) { v = b_ih[r] + b_hh[r]; lo = 1; }
        else if (k < 151) { v = W_ih[r * 7 + (k - 144)]; lo = 1; }
        __half hv = __float2half_rn(v);
        if (lo) hv = __float2half_rn(v - __half2float(hv));
        *(__half*)(sm + OFF_B + n * SB + k * 2) = hv;
    }
    // zero both A buffers
    for (int idx = tid; idx < (2 * ABUF) / 4; idx += NTHR)
        ((uint32_t*)sm)[idx] = 0u;
    for (int idx = tid; idx < ODIM * HID; idx += NTHR) wfc[idx] = W_fc[idx];
    if (tid < ODIM) bfc[tid] = b_fc[tid];
    __syncthreads();

    // ones in bias slots (both buffers), x(0) into buf0
    if (tid < TB) {
        __half one = __float2half_rn(1.0f);
        #pragma unroll
        for (int bs = 0; bs < 2; ++bs) {
            char* ab = sm + bs * ABUF + tid * SA;
            *(__half*)(ab + 142 * 2) = one;
            *(__half*)(ab + 143 * 2) = one;
        }
    }
    const int is_xw = (w == 0) || (w == 4);
    const int xrow  = hid * 32 + lane;
    const float* xp = x + (size_t)(bbase + xrow) * (T_STEPS * IDIM);
    if (is_xw) {
        char* ab = sm + xrow * SA;
        #pragma unroll
        for (int i = 0; i < IDIM; ++i) {
            float v = xp[i];
            __half hh = __float2half_rn(v);
            __half hl = __float2half_rn(v - __half2float(hh));
            *(__half*)(ab + (128 + i) * 2) = hh;
            *(__half*)(ab + (135 + i) * 2) = hl;
        }
    }
    __syncthreads();

    const uint32_t sm32 = smem_u32(sm);
    // per-lane ldmatrix address components
    const uint32_t a_l = (uint32_t)((mrow + (lane & 15)) * SA + ((lane >> 4) << 4));
    const uint32_t b_l = sm32 + OFF_B +
        (uint32_t)((ncol + (lane & 7) + ((lane >> 4) << 3)) * SB + (((lane >> 3) & 1) << 4));

    float cst[16];
    #pragma unroll
    for (int i = 0; i < 16; ++i) cst[i] = 0.f;

    for (int t = 0; t < T_STEPS; ++t) {
        const uint32_t aB = sm32 + (uint32_t)((t & 1) * ABUF);
        char* anext = sm + ((t + 1) & 1) * ABUF;

        float acc[2][8][4];
        #pragma unroll
        for (int mt = 0; mt < 2; ++mt)
            #pragma unroll
            for (int nt = 0; nt < 8; ++nt)
                #pragma unroll
                for (int q = 0; q < 4; ++q) acc[mt][nt][q] = 0.f;

        // keep A chunks 0-3 (h_hi) and 8 (x) in regs
        uint32_t ak[5][2][4];
        #pragma unroll
        for (int c = 0; c < 4; ++c)
            #pragma unroll
            for (int mt = 0; mt < 2; ++mt)
                LDSM4(ak[c][mt], aB + a_l + (uint32_t)(mt * 16 * SA + c * 32));
        #pragma unroll
        for (int mt = 0; mt < 2; ++mt)
            LDSM4(ak[4][mt], aB + a_l + (uint32_t)(mt * 16 * SA + 8 * 32));

        // prefetch x(t+1) during GEMM
        float xr[IDIM];
        const bool dox = is_xw && (t + 1 < T_STEPS);
        if (dox) {
            #pragma unroll
            for (int i = 0; i < IDIM; ++i) xr[i] = __ldg(xp + (t + 1) * IDIM + i);
        }

        uint32_t bb[4][4];
        // pairings: (A_c, B_c) hi*hi, (A_{4+c}, B_c) lo*hi  — reuse B frags
        #pragma unroll
        for (int cb = 0; cb < 4; ++cb) {
            #pragma unroll
            for (int p = 0; p < 4; ++p)
                LDSM4(bb[p], b_l + (uint32_t)(p * 16 * SB + cb * 32));
            #pragma unroll
            for (int mt = 0; mt < 2; ++mt)
                #pragma unroll
                for (int p = 0; p < 4; ++p) {
                    MMA(acc[mt][2 * p],     ak[cb][mt], bb[p][0], bb[p][1]);
                    MMA(acc[mt][2 * p + 1], ak[cb][mt], bb[p][2], bb[p][3]);
                }
            uint32_t at[2][4];
            #pragma unroll
            for (int mt = 0; mt < 2; ++mt)
                LDSM4(at[mt], aB + a_l + (uint32_t)(mt * 16 * SA + (4 + cb) * 32));
            #pragma unroll
            for (int mt = 0; mt < 2; ++mt)
                #pragma unroll
                for (int p = 0; p < 4; ++p) {
                    MMA(acc[mt][2 * p],     at[mt], bb[p][0], bb[p][1]);
                    MMA(acc[mt][2 * p + 1], at[mt], bb[p][2], bb[p][3]);
                }
        }
        // (A_c, B_{4+c}) hi*lo
        #pragma unroll
        for (int cb = 4; cb < 8; ++cb) {
            #pragma unroll
            for (int p = 0; p < 4; ++p)
                LDSM4(bb[p], b_l + (uint32_t)(p * 16 * SB + cb * 32));
            #pragma unroll
            for (int mt = 0; mt < 2; ++mt)
                #pragma unroll
                for (int p = 0; p < 4; ++p) {
                    MMA(acc[mt][2 * p],     ak[cb - 4][mt], bb[p][0], bb[p][1]);
                    MMA(acc[mt][2 * p + 1], ak[cb - 4][mt], bb[p][2], bb[p][3]);
                }
        }
        // x chunks: (A8, B8) and (A8, B9)
        #pragma unroll
        for (int cb = 8; cb < 10; ++cb) {
            #pragma unroll
            for (int p = 0; p < 4; ++p)
                LDSM4(bb[p], b_l + (uint32_t)(p * 16 * SB + cb * 32));
            #pragma unroll
            for (int mt = 0; mt < 2; ++mt)
                #pragma unroll
                for (int p = 0; p < 4; ++p) {
                    MMA(acc[mt][2 * p],     ak[4][mt], bb[p][0], bb[p][1]);
                    MMA(acc[mt][2 * p + 1], ak[4][mt], bb[p][2], bb[p][3]);
                }
        }

        // ---- epilogue: gather i,f,g,o per element via shfl, update c, emit h ----
        const int lodd = lane & 1;
        #pragma unroll
        for (int mt = 0; mt < 2; ++mt)
            #pragma unroll
            for (int nt = 0; nt < 8; ++nt) {
                float a0 = acc[mt][nt][0], a1 = acc[mt][nt][1];
                float a2 = acc[mt][nt][2], a3 = acc[mt][nt][3];
                float s0 = lodd ? a0 : a2;
                float s1 = lodd ? a1 : a3;
                float o0 = __shfl_xor_sync(0xffffffffu, s0, 1);
                float o1 = __shfl_xor_sync(0xffffffffu, s1, 1);
                float iv = lodd ? o0 : a0;
                float fv = lodd ? o1 : a1;
                float gv = lodd ? a2 : o0;
                float ov = lodd ? a3 : o1;
                int ci = mt * 8 + nt;
                float ei = __expf(-iv);
                float ef = __expf(-fv);
                float eo = __expf(-ov);
                float eg = __expf(-2.f * gv);
                float pig = (1.f + ei) * (1.f + eg);
                float cn = __fdividef(cst[ci] * pig + (1.f - eg) * (1.f + ef),
                                      pig * (1.f + ef));
                cst[ci] = cn;
                float ec = __expf(-2.f * cn);
                float hv = __fdividef(1.f - ec, (1.f + eo) * (1.f + ec));
                int row = mrow + mt * 16 + (lane >> 2) + ((lane & 1) << 3);
                int j   = (ncol >> 2) + nt * 2 + ((lane >> 1) & 1);
                __half hh = __float2half_rn(hv);
                __half hl = __float2half_rn(hv - __half2float(hh));
                *(__half*)(anext + row * SA + j * 2)        = hh;
                *(__half*)(anext + row * SA + (64 + j) * 2) = hl;
                if (t == T_STEPS - 1) hf[row * 68 + j] = hv;
            }

        // store x(t+1)
        if (dox) {
            char* ab = anext + xrow * SA;
            #pragma unroll
            for (int i = 0; i < IDIM; ++i) {
                float v = xr[i];
                __half hh = __float2half_rn(v);
                __half hl = __float2half_rn(v - __half2float(hh));
                *(__half*)(ab + (128 + i) * 2) = hh;
                *(__half*)(ab + (135 + i) * 2) = hl;
            }
        }

        asm volatile("bar.sync %0, %1;" :: "r"(hid + 1), "r"(128) : "memory");
    }

    __syncthreads();

    // ---- final FC ----
    if (tid < 128) {
        int b  = tid >> 1;
        int ob = (tid & 1) * 8;
        float acc_o[8];
        #pragma unroll
        for (int oo = 0; oo < 8; ++oo) acc_o[oo] = bfc[ob + oo];
        for (int kk = 0; kk < HID; kk += 4) {
            float4 hv = *(float4*)&hf[b * 68 + kk];
            #pragma unroll
            for (int oo = 0; oo < 8; ++oo) {
                float4 wf = *(float4*)&wfc[(ob + oo) * HID + kk];
                acc_o[oo] += hv.x * wf.x + hv.y * wf.y + hv.z * wf.z + hv.w * wf.w;
            }
        }
        #pragma unroll
        for (int oo = 0; oo < 8; ++oo)
            out[(size_t)(bbase + b) * ODIM + ob + oo] = acc_o[oo];
    }
}

extern "C" void kernel_launch(void* const* d_in, const int* in_sizes, int n_in,
                              void* d_out, int out_size) {
    const float* x    = (const float*)d_in[0];
    const float* W_ih = (const float*)d_in[1];
    const float* W_hh = (const float*)d_in[2];
    const float* b_ih = (const float*)d_in[3];
    const float* b_hh = (const float*)d_in[4];
    const float* W_fc = (const float*)d_in[5];
    const float* b_fc = (const float*)d_in[6];
    float* out = (float*)d_out;

    int B = in_sizes[0] / (T_STEPS * IDIM);   // 8192
    int nblocks = B / TB;                     // 128

    cudaFuncSetAttribute(lstm_mma, cudaFuncAttributeMaxDynamicSharedMemorySize, SMEM_TOTAL);
    lstm_mma<<<nblocks, NTHR, SMEM_TOTAL>>>(x, W_ih, W_hh, b_ih, b_hh, W_fc, b_fc, out);
}

// round 4
// speedup vs baseline: 2.2179x; 1.0231x over previous
#include <cuda_runtime.h>
#include <cuda_fp16.h>
#include <cstdint>

// ShallowLSTM via mma.sync m16n8k16 fp16->fp32, generic PTX.
// B=8192, T=180, I=7, H=64, O=16. 128 CTAs x 64 batch, 512 threads (16 warps).
// 4 independent 16-batch groups per CTA (own named barrier), 4 warps each,
// warp tile 16(M) x 64(N). K=160 split: [h_hi(64)|h_lo(64)|x_hi(7) x_lo(7) 1 1],
// B carries hi/lo weight blocks -> all first-order fp16 residues corrected.

#define T_STEPS 180
#define IDIM    7
#define HID     64
#define TB      64
#define NTHR    512
#define ODIM    16

#define SA      304           // A row stride bytes (144 halves + pad)
#define SB      336           // B row stride bytes (160 halves + pad)
#define ABUF    19456         // 64*SA
#define OFF_B   38912
#define OFF_HF  124928
#define OFF_WFC 142336
#define OFF_BFC 146432
#define SMEM_TOTAL 146496

__device__ __forceinline__ uint32_t smem_u32(const void* p) {
    uint32_t a;
    asm("{ .reg .u64 t; cvta.to.shared.u64 t, %1; cvt.u32.u64 %0, t; }" : "=r"(a) : "l"(p));
    return a;
}

#define LDSM4(r, addr) \
    asm volatile("ldmatrix.sync.aligned.m8n8.x4.shared.b16 {%0,%1,%2,%3}, [%4];" \
        : "=r"((r)[0]), "=r"((r)[1]), "=r"((r)[2]), "=r"((r)[3]) : "r"(addr))

#define MMA(d, a, b0, b1) \
    asm volatile("mma.sync.aligned.m16n8k16.row.col.f32.f16.f16.f32 " \
        "{%0,%1,%2,%3},{%4,%5,%6,%7},{%8,%9},{%0,%1,%2,%3};" \
        : "+f"((d)[0]), "+f"((d)[1]), "+f"((d)[2]), "+f"((d)[3]) \
        : "r"((a)[0]), "r"((a)[1]), "r"((a)[2]), "r"((a)[3]), "r"(b0), "r"(b1))

__global__ void __launch_bounds__(NTHR, 1) lstm_mma(
    const float* __restrict__ x,
    const float* __restrict__ W_ih,
    const float* __restrict__ W_hh,
    const float* __restrict__ b_ih,
    const float* __restrict__ b_hh,
    const float* __restrict__ W_fc,
    const float* __restrict__ b_fc,
    float* __restrict__ out)
{
    extern __shared__ char sm[];
    float* hf  = (float*)(sm + OFF_HF);
    float* wfc = (float*)(sm + OFF_WFC);
    float* bfc = (float*)(sm + OFF_BFC);

    const int tid  = threadIdx.x;
    const int w    = tid >> 5;
    const int lane = tid & 31;
    const int grp  = w >> 2;            // 4 groups of 4 warps, 16 batch rows each
    const int wn   = w & 3;
    const int mrow = grp * 16;
    const int ncol = wn * 64;
    const int bbase = blockIdx.x * TB;

    // ---- build B [256 n][160 k] fp16 (n = 4*j + gate reorder) ----
    for (int idx = tid; idx < 256 * 160; idx += NTHR) {
        int n = idx / 160, k = idx - n * 160;
        int r = (n & 3) * 64 + (n >> 2);
        float v = 0.f; int lo = 0;
        if      (k < 64)  v = W_hh[r * 64 + k];
        else if (k < 128) { v = W_hh[r * 64 + (k - 64)]; lo = 1; }
        else if (k < 135) v = W_ih[r * 7 + (k - 128)];
        else if (k < 142) v = W_ih[r * 7 + (k - 135)];
        else if (k == 142) v = b_ih[r] + b_hh[r];
        else if (k == 143) { v = b_ih[r] + b_hh[r]; lo = 1; }
        else if (k < 151) { v = W_ih[r * 7 + (k - 144)]; lo = 1; }
        __half hv = __float2half_rn(v);
        if (lo) hv = __float2half_rn(v - __half2float(hv));
        *(__half*)(sm + OFF_B + n * SB + k * 2) = hv;
    }
    // zero both A buffers
    for (int idx = tid; idx < (2 * ABUF) / 4; idx += NTHR)
        ((uint32_t*)sm)[idx] = 0u;
    for (int idx = tid; idx < ODIM * HID; idx += NTHR) wfc[idx] = W_fc[idx];
    if (tid < ODIM) bfc[tid] = b_fc[tid];
    __syncthreads();

    // ones in bias slots (both buffers), x(0) into buf0
    if (tid < TB) {
        __half one = __float2half_rn(1.0f);
        #pragma unroll
        for (int bs = 0; bs < 2; ++bs) {
            char* ab = sm + bs * ABUF + tid * SA;
            *(__half*)(ab + 142 * 2) = one;
            *(__half*)(ab + 143 * 2) = one;
        }
    }
    const bool is_xw = (wn == 0) && (lane < 16);
    const int xrow   = mrow + (lane & 15);
    const float* xp  = x + (size_t)(bbase + xrow) * (T_STEPS * IDIM);
    if (is_xw) {
        char* ab = sm + xrow * SA;
        #pragma unroll
        for (int i = 0; i < IDIM; ++i) {
            float v = xp[i];
            __half hh = __float2half_rn(v);
            __half hl = __float2half_rn(v - __half2float(hh));
            *(__half*)(ab + (128 + i) * 2) = hh;
            *(__half*)(ab + (135 + i) * 2) = hl;
        }
    }
    __syncthreads();

    const uint32_t sm32 = smem_u32(sm);
    // per-lane ldmatrix address components
    const uint32_t a_l = (uint32_t)((mrow + (lane & 15)) * SA + ((lane >> 4) << 4));
    const uint32_t b_l = sm32 + OFF_B +
        (uint32_t)((ncol + (lane & 7) + ((lane >> 4) << 3)) * SB + (((lane >> 3) & 1) << 4));

    float cst[8];
    #pragma unroll
    for (int i = 0; i < 8; ++i) cst[i] = 0.f;

    for (int t = 0; t < T_STEPS; ++t) {
        const uint32_t aB = sm32 + (uint32_t)((t & 1) * ABUF);
        char* anext = sm + ((t + 1) & 1) * ABUF;

        float acc[8][4];
        #pragma unroll
        for (int nt = 0; nt < 8; ++nt)
            #pragma unroll
            for (int q = 0; q < 4; ++q) acc[nt][q] = 0.f;

        // keep A chunks 0-3 (h_hi) and 8 (x+bias) in regs
        uint32_t ak[5][4];
        #pragma unroll
        for (int c = 0; c < 4; ++c)
            LDSM4(ak[c], aB + a_l + (uint32_t)(c * 32));
        LDSM4(ak[4], aB + a_l + (uint32_t)(8 * 32));

        // prefetch x(t+1) during GEMM
        float xr[IDIM];
        const bool dox = is_xw && (t + 1 < T_STEPS);
        if (dox) {
            #pragma unroll
            for (int i = 0; i < IDIM; ++i) xr[i] = __ldg(xp + (t + 1) * IDIM + i);
        }

        uint32_t bb[4][4];
        // (A_c, B_c) hi*hi and (A_{4+c}, B_c) lo*hi — reuse B frags
        #pragma unroll
        for (int cb = 0; cb < 4; ++cb) {
            #pragma unroll
            for (int p = 0; p < 4; ++p)
                LDSM4(bb[p], b_l + (uint32_t)(p * 16 * SB + cb * 32));
            #pragma unroll
            for (int p = 0; p < 4; ++p) {
                MMA(acc[2 * p],     ak[cb], bb[p][0], bb[p][1]);
                MMA(acc[2 * p + 1], ak[cb], bb[p][2], bb[p][3]);
            }
            uint32_t at[4];
            LDSM4(at, aB + a_l + (uint32_t)((4 + cb) * 32));
            #pragma unroll
            for (int p = 0; p < 4; ++p) {
                MMA(acc[2 * p],     at, bb[p][0], bb[p][1]);
                MMA(acc[2 * p + 1], at, bb[p][2], bb[p][3]);
            }
        }
        // (A_c, B_{4+c}) hi*lo
        #pragma unroll
        for (int cb = 4; cb < 8; ++cb) {
            #pragma unroll
            for (int p = 0; p < 4; ++p)
                LDSM4(bb[p], b_l + (uint32_t)(p * 16 * SB + cb * 32));
            #pragma unroll
            for (int p = 0; p < 4; ++p) {
                MMA(acc[2 * p],     ak[cb - 4], bb[p][0], bb[p][1]);
                MMA(acc[2 * p + 1], ak[cb - 4], bb[p][2], bb[p][3]);
            }
        }
        // x/bias chunks: (A8, B8) and (A8, B9)
        #pragma unroll
        for (int cb = 8; cb < 10; ++cb) {
            #pragma unroll
            for (int p = 0; p < 4; ++p)
                LDSM4(bb[p], b_l + (uint32_t)(p * 16 * SB + cb * 32));
            #pragma unroll
            for (int p = 0; p < 4; ++p) {
                MMA(acc[2 * p],     ak[4], bb[p][0], bb[p][1]);
                MMA(acc[2 * p + 1], ak[4], bb[p][2], bb[p][3]);
            }
        }

        // ---- epilogue: gather i,f,g,o per element via shfl, update c, emit h ----
        const int lodd = lane & 1;
        #pragma unroll
        for (int nt = 0; nt < 8; ++nt) {
            float a0 = acc[nt][0], a1 = acc[nt][1];
            float a2 = acc[nt][2], a3 = acc[nt][3];
            float s0 = lodd ? a0 : a2;
            float s1 = lodd ? a1 : a3;
            float o0 = __shfl_xor_sync(0xffffffffu, s0, 1);
            float o1 = __shfl_xor_sync(0xffffffffu, s1, 1);
            float iv = lodd ? o0 : a0;
            float fv = lodd ? o1 : a1;
            float gv = lodd ? a2 : o0;
            float ov = lodd ? a3 : o1;
            float ei = __expf(-iv);
            float ef = __expf(-fv);
            float eo = __expf(-ov);
            float eg = __expf(-2.f * gv);
            float pig = (1.f + ei) * (1.f + eg);
            float cn = __fdividef(cst[nt] * pig + (1.f - eg) * (1.f + ef),
                                  pig * (1.f + ef));
            cst[nt] = cn;
            float ec = __expf(-2.f * cn);
            float hv = __fdividef(1.f - ec, (1.f + eo) * (1.f + ec));
            int row = mrow + (lane >> 2) + ((lane & 1) << 3);
            int j   = (ncol >> 2) + nt * 2 + ((lane >> 1) & 1);
            __half hh = __float2half_rn(hv);
            __half hl = __float2half_rn(hv - __half2float(hh));
            *(__half*)(anext + row * SA + j * 2)        = hh;
            *(__half*)(anext + row * SA + (64 + j) * 2) = hl;
            if (t == T_STEPS - 1) hf[row * 68 + j] = hv;
        }

        // store x(t+1)
        if (dox) {
            char* ab = anext + xrow * SA;
            #pragma unroll
            for (int i = 0; i < IDIM; ++i) {
                float v = xr[i];
                __half hh = __float2half_rn(v);
                __half hl = __float2half_rn(v - __half2float(hh));
                *(__half*)(ab + (128 + i) * 2) = hh;
                *(__half*)(ab + (135 + i) * 2) = hl;
            }
        }

        asm volatile("bar.sync %0, %1;" :: "r"(grp + 1), "r"(128) : "memory");
    }

    __syncthreads();

    // ---- final FC ----
    if (tid < 128) {
        int b  = tid >> 1;
        int ob = (tid & 1) * 8;
        float acc_o[8];
        #pragma unroll
        for (int oo = 0; oo < 8; ++oo) acc_o[oo] = bfc[ob + oo];
        for (int kk = 0; kk < HID; kk += 4) {
            float4 hv = *(float4*)&hf[b * 68 + kk];
            #pragma unroll
            for (int oo = 0; oo < 8; ++oo) {
                float4 wf = *(float4*)&wfc[(ob + oo) * HID + kk];
                acc_o[oo] += hv.x * wf.x + hv.y * wf.y + hv.z * wf.z + hv.w * wf.w;
            }
        }
        #pragma unroll
        for (int oo = 0; oo < 8; ++oo)
            out[(size_t)(bbase + b) * ODIM + ob + oo] = acc_o[oo];
    }
}

extern "C" void kernel_launch(void* const* d_in, const int* in_sizes, int n_in,
                              void* d_out, int out_size) {
    const float* x    = (const float*)d_in[0];
    const float* W_ih = (const float*)d_in[1];
    const float* W_hh = (const float*)d_in[2];
    const float* b_ih = (const float*)d_in[3];
    const float* b_hh = (const float*)d_in[4];
    const float* W_fc = (const float*)d_in[5];
    const float* b_fc = (const float*)d_in[6];
    float* out = (float*)d_out;

    int B = in_sizes[0] / (T_STEPS * IDIM);   // 8192
    int nblocks = B / TB;                     // 128

    cudaFuncSetAttribute(lstm_mma, cudaFuncAttributeMaxDynamicSharedMemorySize, SMEM_TOTAL);
    lstm_mma<<<nblocks, NTHR, SMEM_TOTAL>>>(x, W_ih, W_hh, b_ih, b_hh, W_fc, b_fc, out);
}

// round 5
// speedup vs baseline: 2.2523x; 1.0155x over previous
#include <cuda_runtime.h>
#include <cuda_fp16.h>
#include <cstdint>

// ShallowLSTM via mma.sync m16n8k16 fp16->fp32, generic PTX.
// B=8192, T=180, I=7, H=64, O=16. 128 CTAs x 64 batch, 512 threads (16 warps).
// 4 independent 16-batch groups (own named barrier), warp tile 16M x 64N.
// K=160 split: [h_hi(64)|h_lo(64)|x_hi(7) x_lo(7) 1 1]; hi/lo weight blocks
// correct all first-order fp16 residues (fp32-class).
// Step is software-pipelined: MMA stream of n-tile p+1 issues before the
// epilogue of tile p, overlapping tensor pipe with MUFU/FMA epilogue.

#define T_STEPS 180
#define IDIM    7
#define HID     64
#define TB      64
#define NTHR    512
#define ODIM    16

#define SA      304           // A row stride bytes (144 halves + pad)
#define SB      336           // B row stride bytes (160 halves + pad)
#define ABUF    19456         // 64*SA
#define OFF_B   38912
#define OFF_HF  124928
#define OFF_WFC 142336
#define OFF_BFC 146432
#define SMEM_TOTAL 146496

__device__ __forceinline__ uint32_t smem_u32(const void* p) {
    uint32_t a;
    asm("{ .reg .u64 t; cvta.to.shared.u64 t, %1; cvt.u32.u64 %0, t; }" : "=r"(a) : "l"(p));
    return a;
}

#define LDSM4(r, addr) \
    asm volatile("ldmatrix.sync.aligned.m8n8.x4.shared.b16 {%0,%1,%2,%3}, [%4];" \
        : "=r"((r)[0]), "=r"((r)[1]), "=r"((r)[2]), "=r"((r)[3]) : "r"(addr))

#define MMA(d, a, b0, b1) \
    asm volatile("mma.sync.aligned.m16n8k16.row.col.f32.f16.f16.f32 " \
        "{%0,%1,%2,%3},{%4,%5,%6,%7},{%8,%9},{%0,%1,%2,%3};" \
        : "+f"((d)[0]), "+f"((d)[1]), "+f"((d)[2]), "+f"((d)[3]) \
        : "r"((a)[0]), "r"((a)[1]), "r"((a)[2]), "r"((a)[3]), "r"(b0), "r"(b1))

// One n-tile pass: 10 B-fragment loads + 28 MMAs into acc[2p], acc[2p+1]
#define MMA_PASS(p) do { \
    uint32_t bb[4]; \
    _Pragma("unroll") \
    for (int cb = 0; cb < 4; ++cb) { \
        LDSM4(bb, b_l + (uint32_t)((p) * 16 * SB + cb * 32)); \
        MMA(acc[2*(p)],   ah[cb], bb[0], bb[1]); \
        MMA(acc[2*(p)+1], ah[cb], bb[2], bb[3]); \
        MMA(acc[2*(p)],   al[cb], bb[0], bb[1]); \
        MMA(acc[2*(p)+1], al[cb], bb[2], bb[3]); \
    } \
    _Pragma("unroll") \
    for (int cb = 4; cb < 8; ++cb) { \
        LDSM4(bb, b_l + (uint32_t)((p) * 16 * SB + cb * 32)); \
        MMA(acc[2*(p)],   ah[cb-4], bb[0], bb[1]); \
        MMA(acc[2*(p)+1], ah[cb-4], bb[2], bb[3]); \
    } \
    _Pragma("unroll") \
    for (int cb = 8; cb < 10; ++cb) { \
        LDSM4(bb, b_l + (uint32_t)((p) * 16 * SB + cb * 32)); \
        MMA(acc[2*(p)],   ax, bb[0], bb[1]); \
        MMA(acc[2*(p)+1], ax, bb[2], bb[3]); \
    } \
} while (0)

__global__ void __launch_bounds__(NTHR, 1) lstm_mma(
    const float* __restrict__ x,
    const float* __restrict__ W_ih,
    const float* __restrict__ W_hh,
    const float* __restrict__ b_ih,
    const float* __restrict__ b_hh,
    const float* __restrict__ W_fc,
    const float* __restrict__ b_fc,
    float* __restrict__ out)
{
    extern __shared__ char sm[];
    float* hf  = (float*)(sm + OFF_HF);
    float* wfc = (float*)(sm + OFF_WFC);
    float* bfc = (float*)(sm + OFF_BFC);

    const int tid  = threadIdx.x;
    const int w    = tid >> 5;
    const int lane = tid & 31;
    const int grp  = w >> 2;            // 4 groups of 4 warps, 16 batch rows each
    const int wn   = w & 3;
    const int mrow = grp * 16;
    const int ncol = wn * 64;
    const int bbase = blockIdx.x * TB;

    // ---- build B [256 n][160 k] fp16 (n = 4*j + gate reorder) ----
    for (int idx = tid; idx < 256 * 160; idx += NTHR) {
        int n = idx / 160, k = idx - n * 160;
        int r = (n & 3) * 64 + (n >> 2);
        float v = 0.f; int lo = 0;
        if      (k < 64)  v = W_hh[r * 64 + k];
        else if (k < 128) { v = W_hh[r * 64 + (k - 64)]; lo = 1; }
        else if (k < 135) v = W_ih[r * 7 + (k - 128)];
        else if (k < 142) v = W_ih[r * 7 + (k - 135)];
        else if (k == 142) v = b_ih[r] + b_hh[r];
        else if (k == 143) { v = b_ih[r] + b_hh[r]; lo = 1; }
        else if (k < 151) { v = W_ih[r * 7 + (k - 144)]; lo = 1; }
        __half hv = __float2half_rn(v);
        if (lo) hv = __float2half_rn(v - __half2float(hv));
        *(__half*)(sm + OFF_B + n * SB + k * 2) = hv;
    }
    // zero both A buffers
    for (int idx = tid; idx < (2 * ABUF) / 4; idx += NTHR)
        ((uint32_t*)sm)[idx] = 0u;
    for (int idx = tid; idx < ODIM * HID; idx += NTHR) wfc[idx] = W_fc[idx];
    if (tid < ODIM) bfc[tid] = b_fc[tid];
    __syncthreads();

    // ones in bias slots (both buffers), x(0) into buf0
    if (tid < TB) {
        __half one = __float2half_rn(1.0f);
        #pragma unroll
        for (int bs = 0; bs < 2; ++bs) {
            char* ab = sm + bs * ABUF + tid * SA;
            *(__half*)(ab + 142 * 2) = one;
            *(__half*)(ab + 143 * 2) = one;
        }
    }
    const bool is_xw = (wn == 0) && (lane < 16);
    const int xrow   = mrow + (lane & 15);
    const float* xp  = x + (size_t)(bbase + xrow) * (T_STEPS * IDIM);
    if (is_xw) {
        char* ab = sm + xrow * SA;
        #pragma unroll
        for (int i = 0; i < IDIM; ++i) {
            float v = xp[i];
            __half hh = __float2half_rn(v);
            __half hl = __float2half_rn(v - __half2float(hh));
            *(__half*)(ab + (128 + i) * 2) = hh;
            *(__half*)(ab + (135 + i) * 2) = hl;
        }
    }
    __syncthreads();

    const uint32_t sm32 = smem_u32(sm);
    const uint32_t a_l = (uint32_t)((mrow + (lane & 15)) * SA + ((lane >> 4) << 4));
    const uint32_t b_l = sm32 + OFF_B +
        (uint32_t)((ncol + (lane & 7) + ((lane >> 4) << 3)) * SB + (((lane >> 3) & 1) << 4));

    float cst[8];
    #pragma unroll
    for (int i = 0; i < 8; ++i) cst[i] = 0.f;

    const int lodd = lane & 1;
    const int erow = (lane >> 2) + ((lane & 1) << 3);   // within group
    const int ejc  = (lane >> 1) & 1;

    for (int t = 0; t < T_STEPS; ++t) {
        const uint32_t aB = sm32 + (uint32_t)((t & 1) * ABUF);
        char* anext = sm + ((t + 1) & 1) * ABUF;

        float acc[8][4];
        #pragma unroll
        for (int nt = 0; nt < 8; ++nt)
            #pragma unroll
            for (int q = 0; q < 4; ++q) acc[nt][q] = 0.f;

        // hoist ALL A chunks into registers: hi 0-3, lo 4-7, x/bias 8
        uint32_t ah[4][4], al[4][4], ax[4];
        #pragma unroll
        for (int c = 0; c < 4; ++c) LDSM4(ah[c], aB + a_l + (uint32_t)(c * 32));
        #pragma unroll
        for (int c = 0; c < 4; ++c) LDSM4(al[c], aB + a_l + (uint32_t)((4 + c) * 32));
        LDSM4(ax, aB + a_l + (uint32_t)(8 * 32));

        // prefetch x(t+1) during GEMM
        float xr[IDIM];
        const bool dox = is_xw && (t + 1 < T_STEPS);
        if (dox) {
            #pragma unroll
            for (int i = 0; i < IDIM; ++i) xr[i] = __ldg(xp + (t + 1) * IDIM + i);
        }

        // ---- pipelined: MMA(p+1) issues before epilogue(p) ----
        MMA_PASS(0);
        #pragma unroll
        for (int p = 0; p < 4; ++p) {
            if (p < 3) MMA_PASS(p + 1);

            // epilogue for tiles nt = 2p, 2p+1
            #pragma unroll
            for (int s = 0; s < 2; ++s) {
                const int nt = 2 * p + s;
                float a0 = acc[nt][0], a1 = acc[nt][1];
                float a2 = acc[nt][2], a3 = acc[nt][3];
                float s0 = lodd ? a0 : a2;
                float s1 = lodd ? a1 : a3;
                float o0 = __shfl_xor_sync(0xffffffffu, s0, 1);
                float o1 = __shfl_xor_sync(0xffffffffu, s1, 1);
                float iv = lodd ? o0 : a0;
                float fv = lodd ? o1 : a1;
                float gv = lodd ? a2 : o0;
                float ov = lodd ? a3 : o1;
                float ei = __expf(-iv);
                float ef = __expf(-fv);
                float eo = __expf(-ov);
                float eg = __expf(-2.f * gv);
                float pig = (1.f + ei) * (1.f + eg);
                float cn = __fdividef(cst[nt] * pig + (1.f - eg) * (1.f + ef),
                                      pig * (1.f + ef));
                cst[nt] = cn;
                float ec = __expf(-2.f * cn);
                float hv = __fdividef(1.f - ec, (1.f + eo) * (1.f + ec));
                int row = mrow + erow;
                int j   = (ncol >> 2) + nt * 2 + ejc;
                __half hh = __float2half_rn(hv);
                __half hl = __float2half_rn(hv - __half2float(hh));
                *(__half*)(anext + row * SA + j * 2)        = hh;
                *(__half*)(anext + row * SA + (64 + j) * 2) = hl;
                if (t == T_STEPS - 1) hf[row * 68 + j] = hv;
            }
        }

        // store x(t+1)
        if (dox) {
            char* ab = anext + xrow * SA;
            #pragma unroll
            for (int i = 0; i < IDIM; ++i) {
                float v = xr[i];
                __half hh = __float2half_rn(v);
                __half hl = __float2half_rn(v - __half2float(hh));
                *(__half*)(ab + (128 + i) * 2) = hh;
                *(__half*)(ab + (135 + i) * 2) = hl;
            }
        }

        asm volatile("bar.sync %0, %1;" :: "r"(grp + 1), "r"(128) : "memory");
    }

    __syncthreads();

    // ---- final FC ----
    if (tid < 128) {
        int b  = tid >> 1;
        int ob = (tid & 1) * 8;
        float acc_o[8];
        #pragma unroll
        for (int oo = 0; oo < 8; ++oo) acc_o[oo] = bfc[ob + oo];
        for (int kk = 0; kk < HID; kk += 4) {
            float4 hv = *(float4*)&hf[b * 68 + kk];
            #pragma unroll
            for (int oo = 0; oo < 8; ++oo) {
                float4 wf = *(float4*)&wfc[(ob + oo) * HID + kk];
                acc_o[oo] += hv.x * wf.x + hv.y * wf.y + hv.z * wf.z + hv.w * wf.w;
            }
        }
        #pragma unroll
        for (int oo = 0; oo < 8; ++oo)
            out[(size_t)(bbase + b) * ODIM + ob + oo] = acc_o[oo];
    }
}

extern "C" void kernel_launch(void* const* d_in, const int* in_sizes, int n_in,
                              void* d_out, int out_size) {
    const float* x    = (const float*)d_in[0];
    const float* W_ih = (const float*)d_in[1];
    const float* W_hh = (const float*)d_in[2];
    const float* b_ih = (const float*)d_in[3];
    const float* b_hh = (const float*)d_in[4];
    const float* W_fc = (const float*)d_in[5];
    const float* b_fc = (const float*)d_in[6];
    float* out = (float*)d_out;

    int B = in_sizes[0] / (T_STEPS * IDIM);   // 8192
    int nblocks = B / TB;                     // 128

    cudaFuncSetAttribute(lstm_mma, cudaFuncAttributeMaxDynamicSharedMemorySize, SMEM_TOTAL);
    lstm_mma<<<nblocks, NTHR, SMEM_TOTAL>>>(x, W_ih, W_hh, b_ih, b_hh, W_fc, b_fc, out);
}

// round 6
// speedup vs baseline: 3.0853x; 1.3699x over previous
#include <cuda_runtime.h>
#include <cuda_fp16.h>
#include <cstdint>

// ShallowLSTM via mma.sync m16n8k16 fp16->fp32, generic PTX.
// B=8192, T=180, I=7, H=64, O=16. 128 CTAs x 64 batch, 512 threads (16 warps).
// 4 independent 16-batch groups (own named barrier), warp tile 16M x 64N.
// Reduced split (R6): K=144: [h_hi(64) | x_hi(7) x_hi(7) 1 1 | (B-only) W_lo(64)].
// Terms kept: Wh_hi*h_hi + Wh_lo*h_hi (weight residue, systematic) + x/bias chunk
// (Wx_hi*x_hi + Wx_lo*x_hi + exact bias). Dropped: W*h_lo, W*x_lo (random-walk
// error ~1e-4 << 1e-3 threshold). 72 MMAs/warp/step (was 112).

#define T_STEPS 180
#define IDIM    7
#define HID     64
#define TB      64
#define NTHR    512
#define ODIM    16

#define SA      176           // A row stride bytes (80 halves + pad)
#define SB      304           // B row stride bytes (144 halves + pad)
#define ABUF    11264         // 64*SA
#define OFF_B   22528
#define OFF_HF  100352        // 64*68 floats
#define OFF_WFC 117760
#define OFF_BFC 121856
#define SMEM_TOTAL 121920

__device__ __forceinline__ uint32_t smem_u32(const void* p) {
    uint32_t a;
    asm("{ .reg .u64 t; cvta.to.shared.u64 t, %1; cvt.u32.u64 %0, t; }" : "=r"(a) : "l"(p));
    return a;
}

#define LDSM4(r, addr) \
    asm volatile("ldmatrix.sync.aligned.m8n8.x4.shared.b16 {%0,%1,%2,%3}, [%4];" \
        : "=r"((r)[0]), "=r"((r)[1]), "=r"((r)[2]), "=r"((r)[3]) : "r"(addr))

#define MMA(d, a, b0, b1) \
    asm volatile("mma.sync.aligned.m16n8k16.row.col.f32.f16.f16.f32 " \
        "{%0,%1,%2,%3},{%4,%5,%6,%7},{%8,%9},{%0,%1,%2,%3};" \
        : "+f"((d)[0]), "+f"((d)[1]), "+f"((d)[2]), "+f"((d)[3]) \
        : "r"((a)[0]), "r"((a)[1]), "r"((a)[2]), "r"((a)[3]), "r"(b0), "r"(b1))

// One n-tile pass: 9 B-fragment loads + 18 MMAs into acc[2p], acc[2p+1]
// B chunks: 0-3 = Wh_hi, 4 = [Wx_hi|Wx_lo|b_hi|b_lo], 5-8 = Wh_lo
#define MMA_PASS(p) do { \
    uint32_t bb[4]; \
    _Pragma("unroll") \
    for (int cb = 0; cb < 4; ++cb) { \
        LDSM4(bb, b_l + (uint32_t)((p) * 16 * SB + cb * 32)); \
        MMA(acc[2*(p)],   ah[cb], bb[0], bb[1]); \
        MMA(acc[2*(p)+1], ah[cb], bb[2], bb[3]); \
    } \
    LDSM4(bb, b_l + (uint32_t)((p) * 16 * SB + 4 * 32)); \
    MMA(acc[2*(p)],   ax, bb[0], bb[1]); \
    MMA(acc[2*(p)+1], ax, bb[2], bb[3]); \
    _Pragma("unroll") \
    for (int cb = 5; cb < 9; ++cb) { \
        LDSM4(bb, b_l + (uint32_t)((p) * 16 * SB + cb * 32)); \
        MMA(acc[2*(p)],   ah[cb-5], bb[0], bb[1]); \
        MMA(acc[2*(p)+1], ah[cb-5], bb[2], bb[3]); \
    } \
} while (0)

__global__ void __launch_bounds__(NTHR, 1) lstm_mma(
    const float* __restrict__ x,
    const float* __restrict__ W_ih,
    const float* __restrict__ W_hh,
    const float* __restrict__ b_ih,
    const float* __restrict__ b_hh,
    const float* __restrict__ W_fc,
    const float* __restrict__ b_fc,
    float* __restrict__ out)
{
    extern __shared__ char sm[];
    float* hf  = (float*)(sm + OFF_HF);
    float* wfc = (float*)(sm + OFF_WFC);
    float* bfc = (float*)(sm + OFF_BFC);

    const int tid  = threadIdx.x;
    const int w    = tid >> 5;
    const int lane = tid & 31;
    const int grp  = w >> 2;            // 4 groups of 4 warps, 16 batch rows each
    const int wn   = w & 3;
    const int mrow = grp * 16;
    const int ncol = wn * 64;
    const int bbase = blockIdx.x * TB;

    // ---- build B [256 n][144 k] fp16 (n = 4*j + gate reorder) ----
    for (int idx = tid; idx < 256 * 144; idx += NTHR) {
        int n = idx / 144, k = idx - n * 144;
        int r = (n & 3) * 64 + (n >> 2);
        float v = 0.f; int lo = 0;
        if      (k < 64)  v = W_hh[r * 64 + k];
        else if (k < 71)  v = W_ih[r * 7 + (k - 64)];
        else if (k < 78)  { v = W_ih[r * 7 + (k - 71)]; lo = 1; }
        else if (k == 78) v = b_ih[r] + b_hh[r];
        else if (k == 79) { v = b_ih[r] + b_hh[r]; lo = 1; }
        else              { v = W_hh[r * 64 + (k - 80)]; lo = 1; }
        __half hv = __float2half_rn(v);
        if (lo) hv = __float2half_rn(v - __half2float(hv));
        *(__half*)(sm + OFF_B + n * SB + k * 2) = hv;
    }
    // zero both A buffers
    for (int idx = tid; idx < (2 * ABUF) / 4; idx += NTHR)
        ((uint32_t*)sm)[idx] = 0u;
    for (int idx = tid; idx < ODIM * HID; idx += NTHR) wfc[idx] = W_fc[idx];
    if (tid < ODIM) bfc[tid] = b_fc[tid];
    __syncthreads();

    // ones in bias slots (both buffers), x(0) into buf0
    if (tid < TB) {
        __half one = __float2half_rn(1.0f);
        #pragma unroll
        for (int bs = 0; bs < 2; ++bs) {
            char* ab = sm + bs * ABUF + tid * SA;
            *(__half*)(ab + 78 * 2) = one;
            *(__half*)(ab + 79 * 2) = one;
        }
    }
    const bool is_xw = (wn == 0) && (lane < 16);
    const int xrow   = mrow + (lane & 15);
    const float* xp  = x + (size_t)(bbase + xrow) * (T_STEPS * IDIM);
    if (is_xw) {
        char* ab = sm + xrow * SA;
        #pragma unroll
        for (int i = 0; i < IDIM; ++i) {
            __half hh = __float2half_rn(xp[i]);
            *(__half*)(ab + (64 + i) * 2) = hh;
            *(__half*)(ab + (71 + i) * 2) = hh;   // dup, pairs with Wx_lo
        }
    }
    __syncthreads();

    const uint32_t sm32 = smem_u32(sm);
    const uint32_t a_l = (uint32_t)((mrow + (lane & 15)) * SA + ((lane >> 4) << 4));
    const uint32_t b_l = sm32 + OFF_B +
        (uint32_t)((ncol + (lane & 7) + ((lane >> 4) << 3)) * SB + (((lane >> 3) & 1) << 4));

    float cst[8];
    #pragma unroll
    for (int i = 0; i < 8; ++i) cst[i] = 0.f;

    const int lodd = lane & 1;
    const int erow = (lane >> 2) + ((lane & 1) << 3);   // within group
    const int ejc  = (lane >> 1) & 1;

    for (int t = 0; t < T_STEPS; ++t) {
        const uint32_t aB = sm32 + (uint32_t)((t & 1) * ABUF);
        char* anext = sm + ((t + 1) & 1) * ABUF;

        float acc[8][4];
        #pragma unroll
        for (int nt = 0; nt < 8; ++nt)
            #pragma unroll
            for (int q = 0; q < 4; ++q) acc[nt][q] = 0.f;

        // hoist A chunks: h_hi 0-3, x/bias chunk 4
        uint32_t ah[4][4], ax[4];
        #pragma unroll
        for (int c = 0; c < 4; ++c) LDSM4(ah[c], aB + a_l + (uint32_t)(c * 32));
        LDSM4(ax, aB + a_l + (uint32_t)(4 * 32));

        // prefetch x(t+1) during GEMM
        float xr[IDIM];
        const bool dox = is_xw && (t + 1 < T_STEPS);
        if (dox) {
            #pragma unroll
            for (int i = 0; i < IDIM; ++i) xr[i] = __ldg(xp + (t + 1) * IDIM + i);
        }

        // ---- pipelined: MMA(p+1) issues before epilogue(p) ----
        MMA_PASS(0);
        #pragma unroll
        for (int p = 0; p < 4; ++p) {
            if (p < 3) MMA_PASS(p + 1);

            // epilogue for tiles nt = 2p, 2p+1
            #pragma unroll
            for (int s = 0; s < 2; ++s) {
                const int nt = 2 * p + s;
                float a0 = acc[nt][0], a1 = acc[nt][1];
                float a2 = acc[nt][2], a3 = acc[nt][3];
                float s0 = lodd ? a0 : a2;
                float s1 = lodd ? a1 : a3;
                float o0 = __shfl_xor_sync(0xffffffffu, s0, 1);
                float o1 = __shfl_xor_sync(0xffffffffu, s1, 1);
                float iv = lodd ? o0 : a0;
                float fv = lodd ? o1 : a1;
                float gv = lodd ? a2 : o0;
                float ov = lodd ? a3 : o1;
                float ei = __expf(-iv);
                float ef = __expf(-fv);
                float eo = __expf(-ov);
                float eg = __expf(-2.f * gv);
                float pig = (1.f + ei) * (1.f + eg);
                float cn = __fdividef(cst[nt] * pig + (1.f - eg) * (1.f + ef),
                                      pig * (1.f + ef));
                cst[nt] = cn;
                float ec = __expf(-2.f * cn);
                float hv = __fdividef(1.f - ec, (1.f + eo) * (1.f + ec));
                int row = mrow + erow;
                int j   = (ncol >> 2) + nt * 2 + ejc;
                *(__half*)(anext + row * SA + j * 2) = __float2half_rn(hv);
                if (t == T_STEPS - 1) hf[row * 68 + j] = hv;
            }
        }

        // store x(t+1)
        if (dox) {
            char* ab = anext + xrow * SA;
            #pragma unroll
            for (int i = 0; i < IDIM; ++i) {
                __half hh = __float2half_rn(xr[i]);
                *(__half*)(ab + (64 + i) * 2) = hh;
                *(__half*)(ab + (71 + i) * 2) = hh;
            }
        }

        asm volatile("bar.sync %0, %1;" :: "r"(grp + 1), "r"(128) : "memory");
    }

    __syncthreads();

    // ---- final FC ----
    if (tid < 128) {
        int b  = tid >> 1;
        int ob = (tid & 1) * 8;
        float acc_o[8];
        #pragma unroll
        for (int oo = 0; oo < 8; ++oo) acc_o[oo] = bfc[ob + oo];
        for (int kk = 0; kk < HID; kk += 4) {
            float4 hv = *(float4*)&hf[b * 68 + kk];
            #pragma unroll
            for (int oo = 0; oo < 8; ++oo) {
                float4 wf = *(float4*)&wfc[(ob + oo) * HID + kk];
                acc_o[oo] += hv.x * wf.x + hv.y * wf.y + hv.z * wf.z + hv.w * wf.w;
            }
        }
        #pragma unroll
        for (int oo = 0; oo < 8; ++oo)
            out[(size_t)(bbase + b) * ODIM + ob + oo] = acc_o[oo];
    }
}

extern "C" void kernel_launch(void* const* d_in, const int* in_sizes, int n_in,
                              void* d_out, int out_size) {
    const float* x    = (const float*)d_in[0];
    const float* W_ih = (const float*)d_in[1];
    const float* W_hh = (const float*)d_in[2];
    const float* b_ih = (const float*)d_in[3];
    const float* b_hh = (const float*)d_in[4];
    const float* W_fc = (const float*)d_in[5];
    const float* b_fc = (const float*)d_in[6];
    float* out = (float*)d_out;

    int B = in_sizes[0] / (T_STEPS * IDIM);   // 8192
    int nblocks = B / TB;                     // 128

    cudaFuncSetAttribute(lstm_mma, cudaFuncAttributeMaxDynamicSharedMemorySize, SMEM_TOTAL);
    lstm_mma<<<nblocks, NTHR, SMEM_TOTAL>>>(x, W_ih, W_hh, b_ih, b_hh, W_fc, b_fc, out);
}